// round 16
// baseline (speedup 1.0000x reference)
#include <cuda_runtime.h>
#include <cuda_bf16.h>
#include <cuda_fp16.h>
#include <cstdint>
#include <math.h>

// ---------------- problem constants ----------------
#define Bq    8
#define Tq    16
#define HID   4096
#define HQ    64
#define HKV   8
#define Dh    64
#define QMULT 8
#define TC    4096
#define TTOT  (TC + Tq)    // 4112
#define WIN   128
#define NKEY  (WIN + 1)    // 129
#define QKVD  5120
#define NROW  (Bq * Tq)    // 128
#define SM_SCALE 0.125f

#define S_QKV 3
#define S_OUT 4

#define OUT_ELEMS   ((size_t)NROW * HID)
#define KV_ELEMS    ((size_t)Bq * TTOT * HKV * Dh)

// ---------------- scratch ----------------
__device__ float g_h[NROW * HID];
__device__ float g_qkv[NROW * QKVD];
__device__ float g_attn[NROW * HID];
__device__ float g_part[4 * NROW * QKVD];
__device__ float g_knew[NROW * HKV * Dh];
__device__ float g_vnew[NROW * HKV * Dh];

// ---------------- KV cache copy (R9-exact) ----------------
#define PERB_SHIFT 19
#define CPY_CTAS   128
#define CPY_THREADS 256
#define CPY_TOTAL  (Bq << PERB_SHIFT)
#define CPY_ITERS  (CPY_TOTAL / (CPY_CTAS * CPY_THREADS))   // 128

__global__ __launch_bounds__(CPY_THREADS) void copy_one_kernel(
    const float4* __restrict__ src, float4* __restrict__ dst)
{
    const int dstb = TTOT * HKV * Dh / 4;
    int base = blockIdx.x * CPY_THREADS + threadIdx.x;
    const int NT = CPY_CTAS * CPY_THREADS;
#pragma unroll 8
    for (int j = 0; j < CPY_ITERS; j++) {
        int i = base + j * NT;
        int b = i >> PERB_SHIFT;
        int r = i & ((1 << PERB_SHIFT) - 1);
        dst[b * dstb + r] = src[i];
    }
}

// ---------------- rmsnorm ----------------
__global__ __launch_bounds__(256) void rmsnorm_kernel(
    const float* __restrict__ x, const float* __restrict__ w, float* __restrict__ h)
{
    int row = blockIdx.x;
    const float* xr = x + (size_t)row * HID;
    float* hr = h + (size_t)row * HID;
    float ss = 0.f;
    for (int i = threadIdx.x; i < HID; i += 256) {
        float v = xr[i];
        ss += v * v;
    }
    __shared__ float red[256];
    red[threadIdx.x] = ss;
    __syncthreads();
    for (int s = 128; s > 0; s >>= 1) {
        if (threadIdx.x < s) red[threadIdx.x] += red[threadIdx.x + s];
        __syncthreads();
    }
    float inv = rsqrtf(red[0] / (float)HID + 1e-5f);
    for (int i = threadIdx.x; i < HID; i += 256)
        hr[i] = xr[i] * inv * w[i];
}

// ---------------- fp16 mma helpers ----------------
__device__ __forceinline__ uint32_t pack_h2(float x, float y) {
    __half2 h = __floats2half2_rn(x, y);
    return *reinterpret_cast<uint32_t*>(&h);
}

#define LDSM_X4(R0, R1, R2, R3, ADDR)                                       \
    asm volatile(                                                           \
        "ldmatrix.sync.aligned.m8n8.x4.shared.b16 {%0,%1,%2,%3}, [%4];"     \
        : "=r"(R0), "=r"(R1), "=r"(R2), "=r"(R3) : "r"(ADDR))

__device__ __forceinline__ void mma_f16(float c[4], const uint32_t a[4],
                                        const uint32_t b[2]) {
    asm volatile(
        "mma.sync.aligned.m16n8k16.row.col.f32.f16.f16.f32 "
        "{%0,%1,%2,%3}, {%4,%5,%6,%7}, {%8,%9}, {%0,%1,%2,%3};\n"
        : "+f"(c[0]), "+f"(c[1]), "+f"(c[2]), "+f"(c[3])
        : "r"(a[0]), "r"(a[1]), "r"(a[2]), "r"(a[3]), "r"(b[0]), "r"(b[1]));
}

__device__ __forceinline__ uint32_t s2u(const void* p) {
    uint32_t r;
    asm("{ .reg .u64 t; cvta.to.shared.u64 t, %1; cvt.u32.u64 %0, t; }"
        : "=r"(r) : "l"(p));
    return r;
}

#define CPASYNC16(dst, src)                                                 \
    asm volatile("cp.async.cg.shared.global [%0], [%1], 16;"                \
                 :: "r"(dst), "l"(src) : "memory")
#define CPCOMMIT() asm volatile("cp.async.commit_group;" ::: "memory")
#define CPWAIT1()  asm volatile("cp.async.wait_group 1;" ::: "memory")

// ---------------- fp16 split-K GEMM: cp.async f32 stage + convert pass ----------------
// BM=128, BN=128, BK=64. 512 threads = 16 warps (4m x 4n), warp tile 32x32.
// f32 staging: 2 stages x (A 32KB + W 32KB) = 128KB. f16 buffer: 2 x 18432 = 36KB.
#define ROWB     144                          // f16 row bytes (64*2 + 16 pad)
#define F16_A    0                            // offsets inside f16 buffer
#define F16_W    (128 * ROWB)                 // 18432
#define F16_BYTES (2 * 128 * ROWB)            // 36864
#define F32_STAGE (2 * 128 * 256)             // 65536 per stage (A+W)
#define GSMEM     (2 * F32_STAGE + F16_BYTES) // 167936

__global__ __launch_bounds__(512, 1) void gemm_f16_splitk(
    const float* __restrict__ A, const float* __restrict__ W,
    float* __restrict__ P, int N, int K)
{
    extern __shared__ char dsm[];
    uint32_t f32base = s2u(dsm);              // [2][A 32KB | W 32KB]
    uint32_t f16base = f32base + 2 * F32_STAGE;

    const int tid = threadIdx.x;
    const int wid = tid >> 5, lane = tid & 31;
    const int wm = (wid >> 2) * 32;           // 0,32,64,96
    const int wn = (wid & 3) * 32;            // 0,32,64,96
    const int bn = blockIdx.x * 128;

    const int kb = K >> 6;
    const int S = gridDim.y;
    const int per = (kb + S - 1) / S;
    const int it0 = blockIdx.y * per;
    const int it1 = min(it0 + per, kb);
    const int nt = it1 - it0;

    // cp.async mapping: 4 threads/row, each 64B (4x16B) per operand
    const int crow = tid >> 2;                // 0..127
    const int cseg = tid & 3;                 // 0..3

#define LOADSTAGE(SB, IT)                                                   \
    {                                                                       \
        uint32_t Sb = f32base + (SB) * F32_STAGE;                           \
        int k0 = ((IT) << 6) + cseg * 16;                                   \
        const float* As = A + (size_t)crow * K + k0;                        \
        const float* Ws = W + (size_t)(bn + crow) * K + k0;                 \
        uint32_t d = crow * 256 + cseg * 64;                                \
        _Pragma("unroll") for (int u = 0; u < 4; u++) {                     \
            CPASYNC16(Sb + d + u * 16, As + u * 4);                         \
            CPASYNC16(Sb + 32768 + d + u * 16, Ws + u * 4);                 \
        }                                                                   \
    }

    float acc[2][4][4];
#pragma unroll
    for (int mi = 0; mi < 2; mi++)
#pragma unroll
        for (int ni = 0; ni < 4; ni++)
#pragma unroll
            for (int r = 0; r < 4; r++) acc[mi][ni][r] = 0.f;

    if (0 < nt) LOADSTAGE(0, it0);
    CPCOMMIT();
    if (1 < nt) LOADSTAGE(1, it0 + 1);
    CPCOMMIT();

    const int a_m = (lane & 7) + (lane & 8);
    const int a_koff = (lane >> 4) * 16;
    const int b_n = (lane & 7) + ((lane >> 4) & 1) * 8;
    const int b_koff = ((lane >> 3) & 1) * 16;

    for (int i = 0; i < nt; i++) {
        int sb = i & 1;
        CPWAIT1();
        __syncthreads();                      // stage sb ready; prev MMA done

        // convert pass: f32 stage -> f16 buffer (linear, conflict-free)
        {
            uint32_t Sb = f32base + sb * F32_STAGE;
            uint32_t rsrc = Sb + crow * 256 + cseg * 64;
            uint32_t wdst = f16base + crow * ROWB + cseg * 32;
#pragma unroll
            for (int op = 0; op < 2; op++) {
                float4 v0, v1, v2, v3;
                asm volatile("ld.shared.v4.f32 {%0,%1,%2,%3}, [%4];"
                             : "=f"(v0.x), "=f"(v0.y), "=f"(v0.z), "=f"(v0.w)
                             : "r"(rsrc));
                asm volatile("ld.shared.v4.f32 {%0,%1,%2,%3}, [%4];"
                             : "=f"(v1.x), "=f"(v1.y), "=f"(v1.z), "=f"(v1.w)
                             : "r"(rsrc + 16));
                asm volatile("ld.shared.v4.f32 {%0,%1,%2,%3}, [%4];"
                             : "=f"(v2.x), "=f"(v2.y), "=f"(v2.z), "=f"(v2.w)
                             : "r"(rsrc + 32));
                asm volatile("ld.shared.v4.f32 {%0,%1,%2,%3}, [%4];"
                             : "=f"(v3.x), "=f"(v3.y), "=f"(v3.z), "=f"(v3.w)
                             : "r"(rsrc + 48));
                uint32_t p0 = pack_h2(v0.x, v0.y), p1 = pack_h2(v0.z, v0.w);
                uint32_t p2 = pack_h2(v1.x, v1.y), p3 = pack_h2(v1.z, v1.w);
                uint32_t p4 = pack_h2(v2.x, v2.y), p5 = pack_h2(v2.z, v2.w);
                uint32_t p6 = pack_h2(v3.x, v3.y), p7 = pack_h2(v3.z, v3.w);
                asm volatile("st.shared.v4.b32 [%0], {%1,%2,%3,%4};"
                             :: "r"(wdst), "r"(p0), "r"(p1), "r"(p2), "r"(p3)
                             : "memory");
                asm volatile("st.shared.v4.b32 [%0], {%1,%2,%3,%4};"
                             :: "r"(wdst + 16), "r"(p4), "r"(p5), "r"(p6), "r"(p7)
                             : "memory");
                rsrc += 32768;
                wdst += F16_W;
            }
        }
        __syncthreads();                      // f16 ready; f32 stage sb free

        int tl = i + 2;
        if (tl < nt) LOADSTAGE(sb, it0 + tl);
        CPCOMMIT();

        // MMA from f16 buffer
        uint32_t Ab = f16base + F16_A;
        uint32_t Bb = f16base + F16_W;
#pragma unroll
        for (int ks = 0; ks < 4; ks++) {
            int kbyte = ks * 32;
            uint32_t af[2][4];
#pragma unroll
            for (int mi = 0; mi < 2; mi++) {
                uint32_t addr = Ab + (wm + mi * 16 + a_m) * ROWB + kbyte + a_koff;
                LDSM_X4(af[mi][0], af[mi][1], af[mi][2], af[mi][3], addr);
            }
            uint32_t bf[4][2];
#pragma unroll
            for (int nj = 0; nj < 2; nj++) {
                uint32_t addr = Bb + (wn + nj * 16 + b_n) * ROWB + kbyte + b_koff;
                LDSM_X4(bf[2 * nj][0], bf[2 * nj][1],
                        bf[2 * nj + 1][0], bf[2 * nj + 1][1], addr);
            }
#pragma unroll
            for (int mi = 0; mi < 2; mi++)
#pragma unroll
                for (int ni = 0; ni < 4; ni++)
                    mma_f16(acc[mi][ni], af[mi], bf[ni]);
        }
        // top-of-loop __syncthreads() separates this MMA from next convert
    }

    const int g = lane >> 2, t = lane & 3;
    float* Pb = P + (size_t)blockIdx.y * NROW * N;
#pragma unroll
    for (int mi = 0; mi < 2; mi++) {
        int r0 = wm + mi * 16 + g;
#pragma unroll
        for (int ni = 0; ni < 4; ni++) {
            int c = bn + wn + ni * 8 + 2 * t;
            *(float2*)(Pb + (size_t)r0 * N + c) =
                make_float2(acc[mi][ni][0], acc[mi][ni][1]);
            *(float2*)(Pb + (size_t)(r0 + 8) * N + c) =
                make_float2(acc[mi][ni][2], acc[mi][ni][3]);
        }
    }
}

// ---------------- fused QKV reduce(+bias, S=S_QKV) + RoPE + K/V scatter ----------------
__global__ __launch_bounds__(256) void reduce_qkv_rope(
    const float* __restrict__ P, const float* __restrict__ bias,
    float* __restrict__ qkv, float* __restrict__ Kout, float* __restrict__ Vout,
    float* __restrict__ knew, float* __restrict__ vnew)
{
    __shared__ float srow[QKVD];
    int row = blockIdx.x;
    int b = row >> 4, t = row & 15, pos = TC + t;
    const int RV4 = QKVD / 4;
    const size_t SPLIT = (size_t)NROW * RV4;
    const float4* P4 = (const float4*)P;
    const float4* B4 = (const float4*)bias;

#pragma unroll
    for (int k = 0; k < 5; k++) {
        int i = threadIdx.x + k * 256;
        size_t off = (size_t)row * RV4 + i;
        float4 a = B4[i];
#pragma unroll
        for (int s = 0; s < S_QKV; s++) {
            float4 p = P4[off + (size_t)s * SPLIT];
            a.x += p.x; a.y += p.y; a.z += p.z; a.w += p.w;
        }
        *(float4*)&srow[i * 4] = a;
    }
    __syncthreads();

    const float NEG_L2T_32 = -0.537331431f;
    for (int p = threadIdx.x; p < 2048 + 256; p += 256) {
        bool isq = (p < 2048);
        int pp = isq ? p : p - 2048;
        int head = pp >> 5, j = pp & 31;
        int base = (isq ? head * 64 : HQ * Dh + head * 64);
        float invf = exp2f((float)j * NEG_L2T_32);
        float ang = (float)pos * invf;
        float c = cosf(ang), s = sinf(ang);
        float x1 = srow[base + j], x2 = srow[base + j + 32];
        float r1 = x1 * c - x2 * s;
        float r2 = x2 * c + x1 * s;
        if (isq) {
            qkv[(size_t)row * QKVD + base + j] = r1;
            qkv[(size_t)row * QKVD + base + j + 32] = r2;
        } else {
            size_t o = ((((size_t)b * TTOT) + pos) * HKV + head) * Dh;
            Kout[o + j] = r1;
            Kout[o + j + 32] = r2;
            size_t on = (((size_t)row * HKV) + head) * Dh;
            knew[on + j] = r1;
            knew[on + j + 32] = r2;
        }
    }
    for (int i = threadIdx.x; i < HKV * Dh; i += 256) {
        float v = srow[(HQ + HKV) * Dh + i];
        Vout[(((size_t)b * TTOT) + pos) * HKV * Dh + i] = v;
        vnew[(size_t)row * HKV * Dh + i] = v;
    }
}

// ---------------- OUT reduce: S_OUT splits + bias + residual ----------------
__global__ __launch_bounds__(256) void reduce_out_kernel(
    const float* __restrict__ P, const float* __restrict__ bias,
    const float* __restrict__ x, float* __restrict__ out)
{
    int i = blockIdx.x * 256 + threadIdx.x;
    const int TOT = NROW * HID / 4;
    const float4* P4 = (const float4*)P;
    float4 bb = ((const float4*)bias)[i & (HID / 4 - 1)];
    float4 rr = ((const float4*)x)[i];
    float4 a = make_float4(bb.x + rr.x, bb.y + rr.y, bb.z + rr.z, bb.w + rr.w);
#pragma unroll
    for (int s = 0; s < S_OUT; s++) {
        float4 p = P4[i + (size_t)s * TOT];
        a.x += p.x; a.y += p.y; a.z += p.z; a.w += p.w;
    }
    ((float4*)out)[i] = a;
}

// ---------------- windowed attention with sink (vectorized, R15) ----------------
#define KVPAD 68
__global__ __launch_bounds__(256) void attn_kernel(
    const float* __restrict__ qkv,
    const float* __restrict__ cache_k, const float* __restrict__ cache_v,
    const float* __restrict__ knew, const float* __restrict__ vnew,
    const float* __restrict__ sinks, float* __restrict__ attn)
{
    int hkv = blockIdx.x;
    int t = blockIdx.y;
    int b = blockIdx.z;
    int row = b * Tq + t;
    int k0 = TC + t - WIN;

    __shared__ float sKV[NKEY * KVPAD];
    __shared__ float sQ[QMULT * Dh];
    __shared__ float sW[QMULT * 132];

    int tid = threadIdx.x;
    int warp = tid >> 5, lane = tid & 31;

    if (tid < 128)
        ((float4*)sQ)[tid] =
            ((const float4*)(qkv + (size_t)row * QKVD + hkv * (QMULT * Dh)))[tid];

    for (int i = tid; i < NKEY * 16; i += 256) {
        int j = i >> 4, d4 = i & 15;
        int kj = k0 + j;
        float4 v;
        if (kj < TC)
            v = *(const float4*)(cache_k +
                    ((((size_t)b * TC + kj) * HKV + hkv) * Dh) + d4 * 4);
        else
            v = *(const float4*)(knew +
                    ((((size_t)b * Tq + (kj - TC)) * HKV + hkv) * Dh) + d4 * 4);
        *(float4*)&sKV[j * KVPAD + d4 * 4] = v;
    }
    __syncthreads();

    float lgv[5];
    float mx = -INFINITY;
#pragma unroll
    for (int i = 0; i < 5; i++) {
        int j = lane + i * 32;
        float acc = -INFINITY;
        if (j < NKEY) {
            acc = 0.f;
            const float4* qq = (const float4*)&sQ[warp * Dh];
            const float4* kk = (const float4*)&sKV[j * KVPAD];
#pragma unroll
            for (int d4 = 0; d4 < 16; d4++) {
                float4 q = qq[d4];
                float4 k = kk[d4];
                acc = fmaf(q.x, k.x, acc);
                acc = fmaf(q.y, k.y, acc);
                acc = fmaf(q.z, k.z, acc);
                acc = fmaf(q.w, k.w, acc);
            }
            acc *= SM_SCALE;
        }
        lgv[i] = acc;
        mx = fmaxf(mx, acc);
    }
#pragma unroll
    for (int o = 16; o > 0; o >>= 1)
        mx = fmaxf(mx, __shfl_xor_sync(0xffffffffu, mx, o));
    float snk = sinks[hkv * QMULT + warp];
    mx = fmaxf(mx, snk);

    float se = 0.f;
#pragma unroll
    for (int i = 0; i < 5; i++) {
        int j = lane + i * 32;
        if (j < NKEY) {
            lgv[i] = expf(lgv[i] - mx);
            se += lgv[i];
        }
    }
#pragma unroll
    for (int o = 16; o > 0; o >>= 1)
        se += __shfl_xor_sync(0xffffffffu, se, o);
    float denom = se + expf(snk - mx);
    float rdenom = 1.f / denom;
#pragma unroll
    for (int i = 0; i < 5; i++) {
        int j = lane + i * 32;
        if (j < NKEY) sW[warp * 132 + j] = lgv[i] * rdenom;
    }
    __syncthreads();

    for (int i = tid; i < NKEY * 16; i += 256) {
        int j = i >> 4, d4 = i & 15;
        int kj = k0 + j;
        float4 v;
        if (kj < TC)
            v = *(const float4*)(cache_v +
                    ((((size_t)b * TC + kj) * HKV + hkv) * Dh) + d4 * 4);
        else
            v = *(const float4*)(vnew +
                    ((((size_t)b * Tq + (kj - TC)) * HKV + hkv) * Dh) + d4 * 4);
        *(float4*)&sKV[j * KVPAD + d4 * 4] = v;
    }
    __syncthreads();

    float a0 = 0.f, a1 = 0.f;
#pragma unroll 4
    for (int j = 0; j < NKEY; j++) {
        float w = sW[warp * 132 + j];
        float2 v = *(const float2*)&sKV[j * KVPAD + lane * 2];
        a0 = fmaf(w, v.x, a0);
        a1 = fmaf(w, v.y, a1);
    }
    size_t ob = (size_t)row * HID + (hkv * QMULT + warp) * Dh;
    attn[ob + lane * 2] = a0;
    attn[ob + lane * 2 + 1] = a1;
}

// ---------------- launch ----------------
extern "C" void kernel_launch(void* const* d_in, const int* in_sizes, int n_in,
                              void* d_out, int out_size)
{
    int sh = 0;
    if (n_in >= 10) sh = 1;
    else if (n_in == 9 && in_sizes[3] == 1) sh = 1;

    const float* x       = (const float*)d_in[0];
    const float* cache_k = (const float*)d_in[1];
    const float* cache_v = (const float*)d_in[2];
    const float* sinks   = (const float*)d_in[3 + sh];
    const float* norm_w  = (const float*)d_in[4 + sh];
    const float* qkv_w   = (const float*)d_in[5 + sh];
    const float* qkv_b   = (const float*)d_in[6 + sh];
    const float* out_w   = (const float*)d_in[7 + sh];
    const float* out_b   = (const float*)d_in[8 + sh];

    float* out  = (float*)d_out;
    float* Kout = out + OUT_ELEMS;
    float* Vout = Kout + KV_ELEMS;

    float *hp, *qkvp, *attnp, *partp, *knp, *vnp;
    cudaGetSymbolAddress((void**)&hp, g_h);
    cudaGetSymbolAddress((void**)&qkvp, g_qkv);
    cudaGetSymbolAddress((void**)&attnp, g_attn);
    cudaGetSymbolAddress((void**)&partp, g_part);
    cudaGetSymbolAddress((void**)&knp, g_knew);
    cudaGetSymbolAddress((void**)&vnp, g_vnew);

    static cudaStream_t s_copy = nullptr;
    static cudaEvent_t ev_fork = nullptr, ev_join = nullptr;
    static int inited = 0;
    if (!inited) {
        cudaStreamCreateWithFlags(&s_copy, cudaStreamNonBlocking);
        cudaEventCreateWithFlags(&ev_fork, cudaEventDisableTiming);
        cudaEventCreateWithFlags(&ev_join, cudaEventDisableTiming);
        cudaFuncSetAttribute(gemm_f16_splitk,
                             cudaFuncAttributeMaxDynamicSharedMemorySize,
                             GSMEM);
        inited = 1;
    }

    // fork: K and V cache copies on side stream (small grids, co-resident)
    cudaEventRecord(ev_fork, 0);
    cudaStreamWaitEvent(s_copy, ev_fork, 0);
    copy_one_kernel<<<CPY_CTAS, CPY_THREADS, 0, s_copy>>>(
        (const float4*)cache_k, (float4*)Kout);
    copy_one_kernel<<<CPY_CTAS, CPY_THREADS, 0, s_copy>>>(
        (const float4*)cache_v, (float4*)Vout);
    cudaEventRecord(ev_join, s_copy);

    // compute chain (gemm_qkv is the 4th launch -> profiled by ncu)
    rmsnorm_kernel<<<NROW, 256>>>(x, norm_w, hp);
    {
        dim3 grid(QKVD / 128, S_QKV);
        gemm_f16_splitk<<<grid, 512, GSMEM>>>(hp, qkv_w, partp, QKVD, HID);
    }
    reduce_qkv_rope<<<NROW, 256>>>(partp, qkv_b, qkvp, Kout, Vout, knp, vnp);
    {
        dim3 grid(HKV, Tq, Bq);
        attn_kernel<<<grid, 256>>>(qkvp, cache_k, cache_v, knp, vnp, sinks, attnp);
    }
    {
        dim3 grid(HID / 128, S_OUT);
        gemm_f16_splitk<<<grid, 512, GSMEM>>>(attnp, out_w, partp, HID, HID);
    }
    reduce_out_kernel<<<NROW * HID / 4 / 256, 256>>>(partp, out_b, x, out);

    cudaStreamWaitEvent(0, ev_join, 0);
}

// round 17
// speedup vs baseline: 1.2467x; 1.2467x over previous
#include <cuda_runtime.h>
#include <cuda_bf16.h>
#include <cuda_fp16.h>
#include <cstdint>
#include <math.h>

// ---------------- problem constants ----------------
#define Bq    8
#define Tq    16
#define HID   4096
#define HQ    64
#define HKV   8
#define Dh    64
#define QMULT 8
#define TC    4096
#define TTOT  (TC + Tq)    // 4112
#define WIN   128
#define NKEY  (WIN + 1)    // 129
#define QKVD  5120
#define NROW  (Bq * Tq)    // 128
#define SM_SCALE 0.125f

#define S_QKV 3
#define S_OUT 4

#define OUT_ELEMS   ((size_t)NROW * HID)
#define KV_ELEMS    ((size_t)Bq * TTOT * HKV * Dh)

// ---------------- scratch ----------------
__device__ float g_h[NROW * HID];
__device__ float g_qkv[NROW * QKVD];
__device__ float g_attn[NROW * HID];
__device__ float g_part[4 * NROW * QKVD];
__device__ float g_knew[NROW * HKV * Dh];
__device__ float g_vnew[NROW * HKV * Dh];

// ---------------- KV cache copy (R9-exact) ----------------
#define PERB_SHIFT 19
#define CPY_CTAS   128
#define CPY_THREADS 256
#define CPY_TOTAL  (Bq << PERB_SHIFT)
#define CPY_ITERS  (CPY_TOTAL / (CPY_CTAS * CPY_THREADS))   // 128

__global__ __launch_bounds__(CPY_THREADS) void copy_one_kernel(
    const float4* __restrict__ src, float4* __restrict__ dst)
{
    const int dstb = TTOT * HKV * Dh / 4;
    int base = blockIdx.x * CPY_THREADS + threadIdx.x;
    const int NT = CPY_CTAS * CPY_THREADS;
#pragma unroll 8
    for (int j = 0; j < CPY_ITERS; j++) {
        int i = base + j * NT;
        int b = i >> PERB_SHIFT;
        int r = i & ((1 << PERB_SHIFT) - 1);
        dst[b * dstb + r] = src[i];
    }
}

// ---------------- rmsnorm ----------------
__global__ __launch_bounds__(256) void rmsnorm_kernel(
    const float* __restrict__ x, const float* __restrict__ w, float* __restrict__ h)
{
    int row = blockIdx.x;
    const float* xr = x + (size_t)row * HID;
    float* hr = h + (size_t)row * HID;
    float ss = 0.f;
    for (int i = threadIdx.x; i < HID; i += 256) {
        float v = xr[i];
        ss += v * v;
    }
    __shared__ float red[256];
    red[threadIdx.x] = ss;
    __syncthreads();
    for (int s = 128; s > 0; s >>= 1) {
        if (threadIdx.x < s) red[threadIdx.x] += red[threadIdx.x + s];
        __syncthreads();
    }
    float inv = rsqrtf(red[0] / (float)HID + 1e-5f);
    for (int i = threadIdx.x; i < HID; i += 256)
        hr[i] = xr[i] * inv * w[i];
}

// ---------------- fp16 mma helpers ----------------
__device__ __forceinline__ uint32_t pack_h2(float x, float y) {
    __half2 h = __floats2half2_rn(x, y);
    return *reinterpret_cast<uint32_t*>(&h);
}

#define LDSM_X4(R0, R1, R2, R3, ADDR)                                       \
    asm volatile(                                                           \
        "ldmatrix.sync.aligned.m8n8.x4.shared.b16 {%0,%1,%2,%3}, [%4];"     \
        : "=r"(R0), "=r"(R1), "=r"(R2), "=r"(R3) : "r"(ADDR))

__device__ __forceinline__ void mma_f16(float c[4], const uint32_t a[4],
                                        const uint32_t b[2]) {
    asm volatile(
        "mma.sync.aligned.m16n8k16.row.col.f32.f16.f16.f32 "
        "{%0,%1,%2,%3}, {%4,%5,%6,%7}, {%8,%9}, {%0,%1,%2,%3};\n"
        : "+f"(c[0]), "+f"(c[1]), "+f"(c[2]), "+f"(c[3])
        : "r"(a[0]), "r"(a[1]), "r"(a[2]), "r"(a[3]), "r"(b[0]), "r"(b[1]));
}

__device__ __forceinline__ uint32_t s2u(const void* p) {
    uint32_t r;
    asm("{ .reg .u64 t; cvta.to.shared.u64 t, %1; cvt.u32.u64 %0, t; }"
        : "=r"(r) : "l"(p));
    return r;
}

// ---------------- fp16 split-K GEMM: BM=128, BN=64, BK=64, 2 CTAs/SM ----------
// 256 threads = 8 warps (4m x 2n), warp tile 32x32. grid = (N/64, S).
#define ROWB     144
#define ATILE_B  (128 * ROWB)              // 18432
#define WTILE_B  (64 * ROWB)               // 9216
#define STAGE_BB (ATILE_B + WTILE_B)       // 27648

__global__ __launch_bounds__(256, 2) void gemm_f16_splitk(
    const float* __restrict__ A, const float* __restrict__ W,
    float* __restrict__ P, int N, int K)
{
    extern __shared__ char dsm[];
    uint32_t sbase = s2u(dsm);

    const int tid = threadIdx.x;
    const int wid = tid >> 5, lane = tid & 31;
    const int wm = (wid >> 1) * 32;
    const int wn = (wid & 1) * 32;
    const int bn = blockIdx.x * 64;

    const int kb = K >> 6;
    const int S = gridDim.y;
    const int per = (kb + S - 1) / S;
    const int it0 = blockIdx.y * per;
    const int it1 = min(it0 + per, kb);
    const int nt = it1 - it0;

    const int lrow = tid >> 4;
    const int c4 = tid & 15;

    float acc[2][4][4];
#pragma unroll
    for (int mi = 0; mi < 2; mi++)
#pragma unroll
        for (int ni = 0; ni < 4; ni++)
#pragma unroll
            for (int r = 0; r < 4; r++) acc[mi][ni][r] = 0.f;

    uint2 ra[8], rw[4];

#define LDTILE(IT)                                                          \
    {                                                                       \
        int k0 = ((IT) << 6) + c4 * 4;                                      \
        _Pragma("unroll") for (int p = 0; p < 8; p++) {                     \
            int row = lrow + p * 16;                                        \
            float4 av = *(const float4*)(A + (size_t)row * K + k0);         \
            ra[p] = make_uint2(pack_h2(av.x, av.y), pack_h2(av.z, av.w));   \
        }                                                                   \
        _Pragma("unroll") for (int p = 0; p < 4; p++) {                     \
            int row = lrow + p * 16;                                        \
            float4 wv = *(const float4*)(W + (size_t)(bn + row) * K + k0);  \
            rw[p] = make_uint2(pack_h2(wv.x, wv.y), pack_h2(wv.z, wv.w));   \
        }                                                                   \
    }

#define STTILE(BUF)                                                         \
    {                                                                       \
        uint32_t Abb = sbase + (BUF) * STAGE_BB;                            \
        uint32_t Bbb = Abb + ATILE_B;                                       \
        uint32_t off = lrow * ROWB + c4 * 8;                                \
        _Pragma("unroll") for (int p = 0; p < 8; p++) {                     \
            asm volatile("st.shared.v2.b32 [%0], {%1,%2};"                  \
                         :: "r"(Abb + off + p * (16 * ROWB)),               \
                            "r"(ra[p].x), "r"(ra[p].y) : "memory");         \
        }                                                                   \
        _Pragma("unroll") for (int p = 0; p < 4; p++) {                     \
            asm volatile("st.shared.v2.b32 [%0], {%1,%2};"                  \
                         :: "r"(Bbb + off + p * (16 * ROWB)),               \
                            "r"(rw[p].x), "r"(rw[p].y) : "memory");         \
        }                                                                   \
    }

    LDTILE(it0);
    STTILE(0);
    __syncthreads();

    const int a_m = (lane & 7) + (lane & 8);
    const int a_koff = (lane >> 4) * 16;
    const int b_n = (lane & 7) + ((lane >> 4) & 1) * 8;
    const int b_koff = ((lane >> 3) & 1) * 16;

    int buf = 0;
    for (int it = 0; it < nt; ++it) {
        bool more = (it + 1 < nt);
        if (more) LDTILE(it0 + it + 1);

        uint32_t Ab = sbase + buf * STAGE_BB;
        uint32_t Bb = Ab + ATILE_B;
#pragma unroll
        for (int ks = 0; ks < 4; ks++) {
            int kbyte = ks * 32;
            uint32_t af[2][4];
#pragma unroll
            for (int mi = 0; mi < 2; mi++) {
                uint32_t addr = Ab + (wm + mi * 16 + a_m) * ROWB + kbyte + a_koff;
                LDSM_X4(af[mi][0], af[mi][1], af[mi][2], af[mi][3], addr);
            }
            uint32_t bf[4][2];
#pragma unroll
            for (int nj = 0; nj < 2; nj++) {
                uint32_t addr = Bb + (wn + nj * 16 + b_n) * ROWB + kbyte + b_koff;
                LDSM_X4(bf[2 * nj][0], bf[2 * nj][1],
                        bf[2 * nj + 1][0], bf[2 * nj + 1][1], addr);
            }
#pragma unroll
            for (int mi = 0; mi < 2; mi++)
#pragma unroll
                for (int ni = 0; ni < 4; ni++)
                    mma_f16(acc[mi][ni], af[mi], bf[ni]);
        }
        if (more) STTILE(buf ^ 1);
        __syncthreads();
        buf ^= 1;
    }

    const int g = lane >> 2, t = lane & 3;
    float* Pb = P + (size_t)blockIdx.y * NROW * N;
#pragma unroll
    for (int mi = 0; mi < 2; mi++) {
        int r0 = wm + mi * 16 + g;
#pragma unroll
        for (int ni = 0; ni < 4; ni++) {
            int c = bn + wn + ni * 8 + 2 * t;
            *(float2*)(Pb + (size_t)r0 * N + c) =
                make_float2(acc[mi][ni][0], acc[mi][ni][1]);
            *(float2*)(Pb + (size_t)(r0 + 8) * N + c) =
                make_float2(acc[mi][ni][2], acc[mi][ni][3]);
        }
    }
}

// ---------------- fused QKV reduce(+bias, S=S_QKV) + RoPE + K/V scatter ----------------
__global__ __launch_bounds__(256) void reduce_qkv_rope(
    const float* __restrict__ P, const float* __restrict__ bias,
    float* __restrict__ qkv, float* __restrict__ Kout, float* __restrict__ Vout,
    float* __restrict__ knew, float* __restrict__ vnew)
{
    __shared__ float srow[QKVD];
    int row = blockIdx.x;
    int b = row >> 4, t = row & 15, pos = TC + t;
    const int RV4 = QKVD / 4;
    const size_t SPLIT = (size_t)NROW * RV4;
    const float4* P4 = (const float4*)P;
    const float4* B4 = (const float4*)bias;

#pragma unroll
    for (int k = 0; k < 5; k++) {
        int i = threadIdx.x + k * 256;
        size_t off = (size_t)row * RV4 + i;
        float4 a = B4[i];
#pragma unroll
        for (int s = 0; s < S_QKV; s++) {
            float4 p = P4[off + (size_t)s * SPLIT];
            a.x += p.x; a.y += p.y; a.z += p.z; a.w += p.w;
        }
        *(float4*)&srow[i * 4] = a;
    }
    __syncthreads();

    const float NEG_L2T_32 = -0.537331431f;
    for (int p = threadIdx.x; p < 2048 + 256; p += 256) {
        bool isq = (p < 2048);
        int pp = isq ? p : p - 2048;
        int head = pp >> 5, j = pp & 31;
        int base = (isq ? head * 64 : HQ * Dh + head * 64);
        float invf = exp2f((float)j * NEG_L2T_32);
        float ang = (float)pos * invf;
        float c = cosf(ang), s = sinf(ang);
        float x1 = srow[base + j], x2 = srow[base + j + 32];
        float r1 = x1 * c - x2 * s;
        float r2 = x2 * c + x1 * s;
        if (isq) {
            qkv[(size_t)row * QKVD + base + j] = r1;
            qkv[(size_t)row * QKVD + base + j + 32] = r2;
        } else {
            size_t o = ((((size_t)b * TTOT) + pos) * HKV + head) * Dh;
            Kout[o + j] = r1;
            Kout[o + j + 32] = r2;
            size_t on = (((size_t)row * HKV) + head) * Dh;
            knew[on + j] = r1;
            knew[on + j + 32] = r2;
        }
    }
    for (int i = threadIdx.x; i < HKV * Dh; i += 256) {
        float v = srow[(HQ + HKV) * Dh + i];
        Vout[(((size_t)b * TTOT) + pos) * HKV * Dh + i] = v;
        vnew[(size_t)row * HKV * Dh + i] = v;
    }
}

// ---------------- OUT reduce: S_OUT splits + bias + residual ----------------
__global__ __launch_bounds__(256) void reduce_out_kernel(
    const float* __restrict__ P, const float* __restrict__ bias,
    const float* __restrict__ x, float* __restrict__ out)
{
    int i = blockIdx.x * 256 + threadIdx.x;
    const int TOT = NROW * HID / 4;
    const float4* P4 = (const float4*)P;
    float4 bb = ((const float4*)bias)[i & (HID / 4 - 1)];
    float4 rr = ((const float4*)x)[i];
    float4 a = make_float4(bb.x + rr.x, bb.y + rr.y, bb.z + rr.z, bb.w + rr.w);
#pragma unroll
    for (int s = 0; s < S_OUT; s++) {
        float4 p = P4[i + (size_t)s * TOT];
        a.x += p.x; a.y += p.y; a.z += p.z; a.w += p.w;
    }
    ((float4*)out)[i] = a;
}

// ---------------- windowed attention with sink (vectorized, R15) ----------------
#define KVPAD 68
__global__ __launch_bounds__(256) void attn_kernel(
    const float* __restrict__ qkv,
    const float* __restrict__ cache_k, const float* __restrict__ cache_v,
    const float* __restrict__ knew, const float* __restrict__ vnew,
    const float* __restrict__ sinks, float* __restrict__ attn)
{
    int hkv = blockIdx.x;
    int t = blockIdx.y;
    int b = blockIdx.z;
    int row = b * Tq + t;
    int k0 = TC + t - WIN;

    __shared__ float sKV[NKEY * KVPAD];
    __shared__ float sQ[QMULT * Dh];
    __shared__ float sW[QMULT * 132];

    int tid = threadIdx.x;
    int warp = tid >> 5, lane = tid & 31;

    if (tid < 128)
        ((float4*)sQ)[tid] =
            ((const float4*)(qkv + (size_t)row * QKVD + hkv * (QMULT * Dh)))[tid];

    for (int i = tid; i < NKEY * 16; i += 256) {
        int j = i >> 4, d4 = i & 15;
        int kj = k0 + j;
        float4 v;
        if (kj < TC)
            v = *(const float4*)(cache_k +
                    ((((size_t)b * TC + kj) * HKV + hkv) * Dh) + d4 * 4);
        else
            v = *(const float4*)(knew +
                    ((((size_t)b * Tq + (kj - TC)) * HKV + hkv) * Dh) + d4 * 4);
        *(float4*)&sKV[j * KVPAD + d4 * 4] = v;
    }
    __syncthreads();

    float lgv[5];
    float mx = -INFINITY;
#pragma unroll
    for (int i = 0; i < 5; i++) {
        int j = lane + i * 32;
        float acc = -INFINITY;
        if (j < NKEY) {
            acc = 0.f;
            const float4* qq = (const float4*)&sQ[warp * Dh];
            const float4* kk = (const float4*)&sKV[j * KVPAD];
#pragma unroll
            for (int d4 = 0; d4 < 16; d4++) {
                float4 q = qq[d4];
                float4 k = kk[d4];
                acc = fmaf(q.x, k.x, acc);
                acc = fmaf(q.y, k.y, acc);
                acc = fmaf(q.z, k.z, acc);
                acc = fmaf(q.w, k.w, acc);
            }
            acc *= SM_SCALE;
        }
        lgv[i] = acc;
        mx = fmaxf(mx, acc);
    }
#pragma unroll
    for (int o = 16; o > 0; o >>= 1)
        mx = fmaxf(mx, __shfl_xor_sync(0xffffffffu, mx, o));
    float snk = sinks[hkv * QMULT + warp];
    mx = fmaxf(mx, snk);

    float se = 0.f;
#pragma unroll
    for (int i = 0; i < 5; i++) {
        int j = lane + i * 32;
        if (j < NKEY) {
            lgv[i] = expf(lgv[i] - mx);
            se += lgv[i];
        }
    }
#pragma unroll
    for (int o = 16; o > 0; o >>= 1)
        se += __shfl_xor_sync(0xffffffffu, se, o);
    float denom = se + expf(snk - mx);
    float rdenom = 1.f / denom;
#pragma unroll
    for (int i = 0; i < 5; i++) {
        int j = lane + i * 32;
        if (j < NKEY) sW[warp * 132 + j] = lgv[i] * rdenom;
    }
    __syncthreads();

    for (int i = tid; i < NKEY * 16; i += 256) {
        int j = i >> 4, d4 = i & 15;
        int kj = k0 + j;
        float4 v;
        if (kj < TC)
            v = *(const float4*)(cache_v +
                    ((((size_t)b * TC + kj) * HKV + hkv) * Dh) + d4 * 4);
        else
            v = *(const float4*)(vnew +
                    ((((size_t)b * Tq + (kj - TC)) * HKV + hkv) * Dh) + d4 * 4);
        *(float4*)&sKV[j * KVPAD + d4 * 4] = v;
    }
    __syncthreads();

    float a0 = 0.f, a1 = 0.f;
#pragma unroll 4
    for (int j = 0; j < NKEY; j++) {
        float w = sW[warp * 132 + j];
        float2 v = *(const float2*)&sKV[j * KVPAD + lane * 2];
        a0 = fmaf(w, v.x, a0);
        a1 = fmaf(w, v.y, a1);
    }
    size_t ob = (size_t)row * HID + (hkv * QMULT + warp) * Dh;
    attn[ob + lane * 2] = a0;
    attn[ob + lane * 2 + 1] = a1;
}

// ---------------- launch ----------------
extern "C" void kernel_launch(void* const* d_in, const int* in_sizes, int n_in,
                              void* d_out, int out_size)
{
    int sh = 0;
    if (n_in >= 10) sh = 1;
    else if (n_in == 9 && in_sizes[3] == 1) sh = 1;

    const float* x       = (const float*)d_in[0];
    const float* cache_k = (const float*)d_in[1];
    const float* cache_v = (const float*)d_in[2];
    const float* sinks   = (const float*)d_in[3 + sh];
    const float* norm_w  = (const float*)d_in[4 + sh];
    const float* qkv_w   = (const float*)d_in[5 + sh];
    const float* qkv_b   = (const float*)d_in[6 + sh];
    const float* out_w   = (const float*)d_in[7 + sh];
    const float* out_b   = (const float*)d_in[8 + sh];

    float* out  = (float*)d_out;
    float* Kout = out + OUT_ELEMS;
    float* Vout = Kout + KV_ELEMS;

    float *hp, *qkvp, *attnp, *partp, *knp, *vnp;
    cudaGetSymbolAddress((void**)&hp, g_h);
    cudaGetSymbolAddress((void**)&qkvp, g_qkv);
    cudaGetSymbolAddress((void**)&attnp, g_attn);
    cudaGetSymbolAddress((void**)&partp, g_part);
    cudaGetSymbolAddress((void**)&knp, g_knew);
    cudaGetSymbolAddress((void**)&vnp, g_vnew);

    static cudaStream_t s_copy = nullptr;
    static cudaEvent_t ev_fork = nullptr, ev_join = nullptr;
    static int inited = 0;
    if (!inited) {
        cudaStreamCreateWithFlags(&s_copy, cudaStreamNonBlocking);
        cudaEventCreateWithFlags(&ev_fork, cudaEventDisableTiming);
        cudaEventCreateWithFlags(&ev_join, cudaEventDisableTiming);
        cudaFuncSetAttribute(gemm_f16_splitk,
                             cudaFuncAttributeMaxDynamicSharedMemorySize,
                             2 * STAGE_BB);
        inited = 1;
    }
    const int smem_bytes = 2 * STAGE_BB;   // 55296

    // fork: K and V cache copies on side stream (small grids, co-resident)
    cudaEventRecord(ev_fork, 0);
    cudaStreamWaitEvent(s_copy, ev_fork, 0);
    copy_one_kernel<<<CPY_CTAS, CPY_THREADS, 0, s_copy>>>(
        (const float4*)cache_k, (float4*)Kout);
    copy_one_kernel<<<CPY_CTAS, CPY_THREADS, 0, s_copy>>>(
        (const float4*)cache_v, (float4*)Vout);
    cudaEventRecord(ev_join, s_copy);

    // compute chain (gemm_qkv is the 4th launch -> profiled by ncu)
    rmsnorm_kernel<<<NROW, 256>>>(x, norm_w, hp);
    {
        dim3 grid(QKVD / 64, S_QKV);
        gemm_f16_splitk<<<grid, 256, smem_bytes>>>(hp, qkv_w, partp, QKVD, HID);
    }
    reduce_qkv_rope<<<NROW, 256>>>(partp, qkv_b, qkvp, Kout, Vout, knp, vnp);
    {
        dim3 grid(HKV, Tq, Bq);
        attn_kernel<<<grid, 256>>>(qkvp, cache_k, cache_v, knp, vnp, sinks, attnp);
    }
    {
        dim3 grid(HID / 64, S_OUT);
        gemm_f16_splitk<<<grid, 256, smem_bytes>>>(attnp, out_w, partp, HID, HID);
    }
    reduce_out_kernel<<<NROW * HID / 4 / 256, 256>>>(partp, out_b, x, out);

    cudaStreamWaitEvent(0, ev_join, 0);
}